// round 9
// baseline (speedup 1.0000x reference)
#include <cuda_runtime.h>

// Problem constants (fixed by the dataset)
#define NN 50000      // nodes
#define HH 5000       // hyperedges
#define EE 400000     // incidence entries
#define BB 2          // batch
#define CC 64         // channels
#define RR (NN*BB)    // 100000 "rows" (n,b) pairs, r = 2*n + b
#define NBLK 49       // ceil(NN/1024) for the scan

// ---------------------------------------------------------------------------
// Scratch: __device__ globals (no runtime allocation allowed)
// ---------------------------------------------------------------------------
__device__ __align__(16) float g_xw[RR * CC];     // projected features [r][c] (25.6 MB)
__device__ __align__(16) float g_d1[RR];          // dot(xw, att[:C])  per (n,b)
__device__ __align__(16) float g_d2[RR];          // dot(xw, att[C:])  per (n,b)
__device__ int   g_Dn[NN];                        // node degree
__device__ int   g_De[HH];                        // hyperedge degree
__device__ int   g_hstart[HH];                    // start offset per hyperedge (hedge sorted)
__device__ int   g_nstart[NN];                    // start offset per node (after scan)
__device__ int   g_cursor[NN];                    // scatter cursors
__device__ int   g_perm[EE];                      // node-sorted permutation of incidences
__device__ __align__(16) float g_aedge[HH * 2];   // per-hyperedge attention scalar
__device__ __align__(16) float g_alpha[EE * 2];   // normalized attention [e][b]
__device__ __align__(16) float g_m[HH * 128];     // hyperedge messages [h][b*64+c] (2.56 MB)
__device__ int   g_bsum[64];                      // scan block sums

// ---------------------------------------------------------------------------
// K0: zero counters
// ---------------------------------------------------------------------------
__global__ void k_zero() {
    int i = blockIdx.x * blockDim.x + threadIdx.x;
    if (i < NN) { g_Dn[i] = 0; g_cursor[i] = 0; }
    if (i < HH) { g_De[i] = 0; }
}

// ---------------------------------------------------------------------------
// K1: GEMM  xw[r][d] = sum_c x[b][n][c] * W[c][d],  r = 2n+b
//     + per-row dots d1[r] = xw[r]·att1, d2[r] = xw[r]·att2
// Block: 256 threads handle 16 rows x 16 thread-groups of 4 channels.
// ---------------------------------------------------------------------------
__global__ void k_gemm(const float* __restrict__ x,
                       const float* __restrict__ W,
                       const float* __restrict__ att) {
    __shared__ float Ws[64 * 64];
    __shared__ float xs[16 * 68];   // stride 68 floats: 16B aligned, conflict-free

    int tid = threadIdx.x;
    // load weight (4096 floats = 1024 float4)
    for (int i = tid; i < 1024; i += 256)
        ((float4*)Ws)[i] = ((const float4*)W)[i];

    int rowblock = blockIdx.x * 16;
    {
        int rl = tid >> 4;          // 0..15 local row
        int cq = tid & 15;          // float4 index within row
        int r  = rowblock + rl;
        float4 v = make_float4(0.f, 0.f, 0.f, 0.f);
        if (r < RR) {
            int n = r >> 1, b = r & 1;
            v = ((const float4*)(x + (size_t)b * NN * 64 + (size_t)n * 64))[cq];
        }
        ((float4*)(xs + rl * 68))[cq] = v;
    }
    __syncthreads();

    int rl = tid >> 4;
    int r  = rowblock + rl;
    int d0 = (tid & 15) * 4;
    float4 acc = make_float4(0.f, 0.f, 0.f, 0.f);
#pragma unroll
    for (int c = 0; c < 64; c++) {
        float  xv = xs[rl * 68 + c];
        float4 w  = *(const float4*)(Ws + c * 64 + d0);
        acc.x += xv * w.x; acc.y += xv * w.y;
        acc.z += xv * w.z; acc.w += xv * w.w;
    }
    if (r < RR) {
        *(float4*)(g_xw + (size_t)r * 64 + d0) = acc;
        float p1 = acc.x * __ldg(att + d0)      + acc.y * __ldg(att + d0 + 1)
                 + acc.z * __ldg(att + d0 + 2)  + acc.w * __ldg(att + d0 + 3);
        float p2 = acc.x * __ldg(att + 64 + d0)     + acc.y * __ldg(att + 64 + d0 + 1)
                 + acc.z * __ldg(att + 64 + d0 + 2) + acc.w * __ldg(att + 64 + d0 + 3);
        // reduce across the 16 lanes owning this row (xor<16 stays in-half)
#pragma unroll
        for (int off = 8; off >= 1; off >>= 1) {
            p1 += __shfl_xor_sync(0xffffffffu, p1, off);
            p2 += __shfl_xor_sync(0xffffffffu, p2, off);
        }
        if ((tid & 15) == 0) { g_d1[r] = p1; g_d2[r] = p2; }
    }
}

// ---------------------------------------------------------------------------
// K2: degrees + hyperedge segment starts (hedge_idx is sorted)
// ---------------------------------------------------------------------------
__global__ void k_deg(const int* __restrict__ node_idx,
                      const int* __restrict__ hedge_idx) {
    int e = blockIdx.x * blockDim.x + threadIdx.x;
    if (e >= EE) return;
    atomicAdd(&g_Dn[node_idx[e]], 1);
    int h = hedge_idx[e];
    atomicAdd(&g_De[h], 1);
    if (e == 0 || hedge_idx[e - 1] != h) g_hstart[h] = e;
}

// ---------------------------------------------------------------------------
// K3a/b/c: exclusive scan of g_Dn -> g_nstart (two-level, 1024-wide blocks)
// ---------------------------------------------------------------------------
__global__ void k_scan1() {
    int i    = blockIdx.x * 1024 + threadIdx.x;
    int lane = threadIdx.x & 31, wid = threadIdx.x >> 5;
    int v = (i < NN) ? g_Dn[i] : 0;
    int x = v;
#pragma unroll
    for (int off = 1; off < 32; off <<= 1) {
        int y = __shfl_up_sync(0xffffffffu, x, off);
        if (lane >= off) x += y;
    }
    __shared__ int ws[32];
    if (lane == 31) ws[wid] = x;
    __syncthreads();
    if (wid == 0) {
        int s = ws[lane];
#pragma unroll
        for (int off = 1; off < 32; off <<= 1) {
            int y = __shfl_up_sync(0xffffffffu, s, off);
            if (lane >= off) s += y;
        }
        ws[lane] = s;
    }
    __syncthreads();
    int excl = x - v + ((wid > 0) ? ws[wid - 1] : 0);
    if (i < NN) g_nstart[i] = excl;
    if (threadIdx.x == 1023) g_bsum[blockIdx.x] = excl + v;
}

__global__ void k_scan2() {
    if (threadIdx.x == 0) {
        int s = 0;
        for (int k = 0; k < NBLK; k++) { int t = g_bsum[k]; g_bsum[k] = s; s += t; }
    }
}

__global__ void k_scan3() {
    int i = blockIdx.x * 1024 + threadIdx.x;
    if (i < NN) g_nstart[i] += g_bsum[blockIdx.x];
}

// ---------------------------------------------------------------------------
// K4: per-hyperedge attention scalar a_edge[h][b] = sum_{e in h} d2[2*node_e + b]
// (eliminates the [H,B,C] edge_sums tensor entirely)
// ---------------------------------------------------------------------------
__global__ void k_aedge(const int* __restrict__ node_idx) {
    int h = blockIdx.x;
    int cnt = g_De[h];
    if (cnt == 0) return;
    int start = g_hstart[h];
    int t = threadIdx.x;            // 128 threads = 4 warps
    float s0 = 0.f, s1 = 0.f;
    for (int i = t; i < cnt; i += 128) {
        int n = node_idx[start + i];
        float2 d = *(const float2*)(g_d2 + 2 * n);
        s0 += d.x; s1 += d.y;
    }
#pragma unroll
    for (int off = 16; off >= 1; off >>= 1) {
        s0 += __shfl_xor_sync(0xffffffffu, s0, off);
        s1 += __shfl_xor_sync(0xffffffffu, s1, off);
    }
    __shared__ float r0[4], r1[4];
    int lane = t & 31, wid = t >> 5;
    if (lane == 0) { r0[wid] = s0; r1[wid] = s1; }
    __syncthreads();
    if (t == 0) {
        float a0 = r0[0] + r0[1] + r0[2] + r0[3];
        float a1 = r1[0] + r1[1] + r1[2] + r1[3];
        g_aedge[2 * h]     = a0;
        g_aedge[2 * h + 1] = a1;
    }
}

// ---------------------------------------------------------------------------
// K5: counting-sort scatter: perm lists incidences grouped by node
// ---------------------------------------------------------------------------
__global__ void k_scatter(const int* __restrict__ node_idx) {
    int e = blockIdx.x * blockDim.x + threadIdx.x;
    if (e >= EE) return;
    int n = node_idx[e];
    int pos = g_nstart[n] + atomicAdd(&g_cursor[n], 1);
    g_perm[pos] = e;
}

// ---------------------------------------------------------------------------
// K6: segment softmax over node segments (warp per node)
// alpha_raw[e][b] = leakyrelu(d1[2n+b] + a_edge[2h+b], 0.2)
// ---------------------------------------------------------------------------
__global__ void k_softmax(const int* __restrict__ hedge_idx) {
    int gw   = (blockIdx.x * blockDim.x + threadIdx.x) >> 5;
    int lane = threadIdx.x & 31;
    if (gw >= NN) return;
    int n = gw, deg = g_Dn[n];
    if (deg == 0) return;
    int start = g_nstart[n];
    float base0 = g_d1[2 * n], base1 = g_d1[2 * n + 1];

    if (deg <= 32) {
        int e = 0;
        float v0 = -1e30f, v1 = -1e30f;
        if (lane < deg) {
            e = g_perm[start + lane];
            int h = hedge_idx[e];
            v0 = base0 + g_aedge[2 * h];
            v1 = base1 + g_aedge[2 * h + 1];
            v0 = (v0 >= 0.f) ? v0 : 0.2f * v0;
            v1 = (v1 >= 0.f) ? v1 : 0.2f * v1;
        }
        float m0 = v0, m1 = v1;
#pragma unroll
        for (int off = 16; off >= 1; off >>= 1) {
            m0 = fmaxf(m0, __shfl_xor_sync(0xffffffffu, m0, off));
            m1 = fmaxf(m1, __shfl_xor_sync(0xffffffffu, m1, off));
        }
        float e0 = (lane < deg) ? __expf(v0 - m0) : 0.f;
        float e1 = (lane < deg) ? __expf(v1 - m1) : 0.f;
        float s0 = e0, s1 = e1;
#pragma unroll
        for (int off = 16; off >= 1; off >>= 1) {
            s0 += __shfl_xor_sync(0xffffffffu, s0, off);
            s1 += __shfl_xor_sync(0xffffffffu, s1, off);
        }
        if (lane < deg) {
            g_alpha[2 * e]     = e0 / s0;
            g_alpha[2 * e + 1] = e1 / s1;
        }
    } else {
        // 3-pass recompute path for rare high-degree nodes
        float m0 = -1e30f, m1 = -1e30f;
        for (int j = lane; j < deg; j += 32) {
            int e = g_perm[start + j]; int h = hedge_idx[e];
            float v0 = base0 + g_aedge[2 * h];
            float v1 = base1 + g_aedge[2 * h + 1];
            v0 = (v0 >= 0.f) ? v0 : 0.2f * v0;
            v1 = (v1 >= 0.f) ? v1 : 0.2f * v1;
            m0 = fmaxf(m0, v0); m1 = fmaxf(m1, v1);
        }
#pragma unroll
        for (int off = 16; off >= 1; off >>= 1) {
            m0 = fmaxf(m0, __shfl_xor_sync(0xffffffffu, m0, off));
            m1 = fmaxf(m1, __shfl_xor_sync(0xffffffffu, m1, off));
        }
        float s0 = 0.f, s1 = 0.f;
        for (int j = lane; j < deg; j += 32) {
            int e = g_perm[start + j]; int h = hedge_idx[e];
            float v0 = base0 + g_aedge[2 * h];
            float v1 = base1 + g_aedge[2 * h + 1];
            v0 = (v0 >= 0.f) ? v0 : 0.2f * v0;
            v1 = (v1 >= 0.f) ? v1 : 0.2f * v1;
            s0 += __expf(v0 - m0); s1 += __expf(v1 - m1);
        }
#pragma unroll
        for (int off = 16; off >= 1; off >>= 1) {
            s0 += __shfl_xor_sync(0xffffffffu, s0, off);
            s1 += __shfl_xor_sync(0xffffffffu, s1, off);
        }
        for (int j = lane; j < deg; j += 32) {
            int e = g_perm[start + j]; int h = hedge_idx[e];
            float v0 = base0 + g_aedge[2 * h];
            float v1 = base1 + g_aedge[2 * h + 1];
            v0 = (v0 >= 0.f) ? v0 : 0.2f * v0;
            v1 = (v1 >= 0.f) ? v1 : 0.2f * v1;
            g_alpha[2 * e]     = __expf(v0 - m0) / s0;
            g_alpha[2 * e + 1] = __expf(v1 - m1) / s1;
        }
    }
}

// ---------------------------------------------------------------------------
// K7: pass1 nodes -> hyperedges: m[h][b*64+c] = (1/De) * sum alpha[e][b]*xw[node]
// block per hyperedge (hedge-sorted -> contiguous segment, no atomics)
// ---------------------------------------------------------------------------
__global__ void k_pass1(const int* __restrict__ node_idx) {
    int h = blockIdx.x;
    int cnt = g_De[h];
    if (cnt == 0) return;
    int start = g_hstart[h];
    int t = threadIdx.x;            // 128 = B*C, thread owns (b,c)
    int b = t >> 6;
    __shared__ int   sn[128];
    __shared__ float sa0[128], sa1[128];
    float acc = 0.f;
    for (int base = 0; base < cnt; base += 128) {
        int mlen = min(128, cnt - base);
        if (t < mlen) {
            int e = start + base + t;
            sn[t] = node_idx[e];
            float2 a = *(const float2*)(g_alpha + 2 * e);
            sa0[t] = a.x; sa1[t] = a.y;
        }
        __syncthreads();
        const float* sa = b ? sa1 : sa0;
#pragma unroll 4
        for (int i = 0; i < mlen; i++) {
            acc += sa[i] * g_xw[(size_t)sn[i] * 128 + t];
        }
        __syncthreads();
    }
    g_m[(size_t)h * 128 + t] = acc / (float)cnt;
}

// ---------------------------------------------------------------------------
// K8: pass2 hyperedges -> nodes: out[b][n][c] = Dn[n] * sum alpha[e][b]*m[h_e]
// warp per node on the node-sorted permutation (no atomics, m is L2-resident)
// ---------------------------------------------------------------------------
__global__ void k_pass2(const int* __restrict__ hedge_idx,
                        float* __restrict__ out) {
    int gw   = (blockIdx.x * blockDim.x + threadIdx.x) >> 5;
    int lane = threadIdx.x & 31;
    if (gw >= NN) return;
    int n = gw, deg = g_Dn[n];
    int start = g_nstart[n];
    float4 acc = make_float4(0.f, 0.f, 0.f, 0.f);

    for (int base = 0; base < deg; base += 32) {
        int cnt = min(32, deg - base);
        int h = 0; float2 a2 = make_float2(0.f, 0.f);
        if (lane < cnt) {
            int e = g_perm[start + base + lane];
            h  = hedge_idx[e];
            a2 = *(const float2*)(g_alpha + 2 * e);
        }
        for (int i = 0; i < cnt; i++) {
            int   hh = __shfl_sync(0xffffffffu, h,    i);
            float a0 = __shfl_sync(0xffffffffu, a2.x, i);
            float a1 = __shfl_sync(0xffffffffu, a2.y, i);
            float a  = (lane < 16) ? a0 : a1;
            float4 mv = *(const float4*)(g_m + (size_t)hh * 128 + lane * 4);
            acc.x += a * mv.x; acc.y += a * mv.y;
            acc.z += a * mv.z; acc.w += a * mv.w;
        }
    }
    float dn = (float)deg;          // Dn multiplies (NOT inverted in source)
    int b  = lane >> 4;
    int c0 = (lane & 15) * 4;
    float4 o = make_float4(dn * acc.x, dn * acc.y, dn * acc.z, dn * acc.w);
    *(float4*)(out + (size_t)b * NN * 64 + (size_t)n * 64 + c0) = o;
}

// ---------------------------------------------------------------------------
// Launch
// ---------------------------------------------------------------------------
extern "C" void kernel_launch(void* const* d_in, const int* in_sizes, int n_in,
                              void* d_out, int out_size) {
    const float* x         = (const float*)d_in[0];   // [B,N,C]
    const float* weight    = (const float*)d_in[1];   // [C,C]
    const float* att       = (const float*)d_in[2];   // [2C]
    const int*   node_idx  = (const int*)d_in[3];     // [E]
    const int*   hedge_idx = (const int*)d_in[4];     // [E] sorted
    float*       out       = (float*)d_out;           // [B,N,C]

    k_zero<<<(NN + 255) / 256, 256>>>();
    k_gemm<<<RR / 16, 256>>>(x, weight, att);
    k_deg<<<(EE + 255) / 256, 256>>>(node_idx, hedge_idx);
    k_scan1<<<NBLK, 1024>>>();
    k_scan2<<<1, 32>>>();
    k_scan3<<<NBLK, 1024>>>();
    k_aedge<<<HH, 128>>>(node_idx);
    k_scatter<<<(EE + 255) / 256, 256>>>(node_idx);
    k_softmax<<<(NN * 32 + 255) / 256, 256>>>(hedge_idx);
    k_pass1<<<HH, 128>>>(node_idx);
    k_pass2<<<(NN * 32 + 255) / 256, 256>>>(hedge_idx, out);
}

// round 11
// speedup vs baseline: 1.2903x; 1.2903x over previous
#include <cuda_runtime.h>
#include <cuda_fp16.h>

// Problem constants (fixed by the dataset)
#define NN 50000      // nodes
#define HH 5000       // hyperedges
#define EE 400000     // incidence entries
#define BB 2          // batch
#define CC 64         // channels
#define RR (NN*BB)    // 100000 (n,b) rows, r = 2n+b
#define RH (HH*BB)    // 10000 hyperedge rows, r' = 2h+b
#define SCAN_CHUNK 391  // ceil(NN/128)

// ---------------------------------------------------------------------------
// Scratch (__device__ globals; no runtime allocation allowed)
// ---------------------------------------------------------------------------
__device__ __align__(16) __half  g_xh[RR * CC];    // fp16 copy of x, row r=2n+b (12.8 MB)
__device__ __align__(16) float   g_d1[RR];         // x . (W@att1)
__device__ __align__(16) float   g_d2[RR];         // x . (W@att2)
__device__ __align__(16) float   g_w[128];         // w1[64], w2[64]
__device__ int   g_Dn[NN];                         // node degree
__device__ int   g_nstart[NN];                     // node segment starts
__device__ int   g_cursor[NN];                     // scatter cursors
__device__ int   g_hstart[HH + 1];                 // hyperedge segment starts (+sentinel)
__device__ __align__(16) float   g_aedge[HH * 2];  // per-hyperedge attention scalar
__device__ int   g_sh[EE];                         // hyperedge id per node-sorted slot
__device__ __align__(16) float   g_ni[NN * 8];     // per-node {d1_0,d1_1,mx0,mx1,inv0,inv1,-,-}
__device__ __align__(16) float   g_agg[HH * 128];  // pre-projection hyperedge agg (fp32)
__device__ __align__(16) __half  g_mh[HH * 128];   // projected messages m (fp16, 1.28 MB)

// ---------------------------------------------------------------------------
// K1: zero counters + compute w1 = W@att1, w2 = W@att2 (block 196)
//     w1[d] = sum_c W[d,c] * att1[c]   (row d of W dotted with att half)
// ---------------------------------------------------------------------------
__global__ void k_init(const float* __restrict__ W, const float* __restrict__ att) {
    if (blockIdx.x == 196) {
        int t = threadIdx.x;
        if (t < 128) {
            int d = t & 63;
            const float* a = att + (t >> 6) * 64;
            float s = 0.f;
#pragma unroll
            for (int c = 0; c < 64; c++) s += W[d * 64 + c] * a[c];   // FIXED: row d, not col d
            g_w[t] = s;
        }
    } else {
        int i = blockIdx.x * 256 + threadIdx.x;
        if (i < NN) { g_Dn[i] = 0; g_cursor[i] = 0; }
    }
}

// ---------------------------------------------------------------------------
// K2: (a) per-row d1,d2 + fp16 quantize of x   (b) node degrees + hstart fill
// ---------------------------------------------------------------------------
#define PREP_BLOCKS 12500
__global__ void k_prep_deg(const float* __restrict__ x,
                           const int* __restrict__ node_idx,
                           const int* __restrict__ hedge_idx) {
    if (blockIdx.x < PREP_BLOCKS) {
        int warp = threadIdx.x >> 5, lane = threadIdx.x & 31;
        int r = blockIdx.x * 8 + warp;          // < RR always (12500*8 = 100000)
        int n = r >> 1, b = r & 1;
        float2 xv = *(const float2*)(x + (size_t)b * NN * 64 + (size_t)n * 64 + lane * 2);
        float2 w1 = *(const float2*)(g_w + 2 * lane);
        float2 w2 = *(const float2*)(g_w + 64 + 2 * lane);
        float p1 = xv.x * w1.x + xv.y * w1.y;
        float p2 = xv.x * w2.x + xv.y * w2.y;
#pragma unroll
        for (int off = 16; off >= 1; off >>= 1) {
            p1 += __shfl_xor_sync(0xffffffffu, p1, off);
            p2 += __shfl_xor_sync(0xffffffffu, p2, off);
        }
        if (lane == 0) { g_d1[r] = p1; g_d2[r] = p2; }
        *(__half2*)(g_xh + (size_t)r * 64 + lane * 2) = __floats2half2_rn(xv.x, xv.y);
    } else {
        int e = (blockIdx.x - PREP_BLOCKS) * 256 + threadIdx.x;
        if (e >= EE) return;
        atomicAdd(&g_Dn[node_idx[e]], 1);
        int h  = hedge_idx[e];
        int hp = (e == 0) ? -1 : hedge_idx[e - 1];
        if (h != hp)
            for (int g = hp + 1; g <= h; g++) g_hstart[g] = e;
        if (e == EE - 1)
            for (int g = h + 1; g <= HH; g++) g_hstart[g] = EE;
    }
}

// ---------------------------------------------------------------------------
// K3: block 0 = single-block exclusive scan of Dn -> nstart
//     blocks 1..HH = aedge[h][b] = sum_{e in h} d2[2*node_e + b]
// ---------------------------------------------------------------------------
__global__ void k_scan_aedge(const int* __restrict__ node_idx) {
    if (blockIdx.x == 0) {
        int t = threadIdx.x;                 // 128 threads
        int begin = t * SCAN_CHUNK;
        int end   = min(begin + SCAN_CHUNK, NN);
        int s = 0;
        for (int i = begin; i < end; i++) s += g_Dn[i];
        int lane = t & 31, wid = t >> 5;
        int xinc = s;
#pragma unroll
        for (int off = 1; off < 32; off <<= 1) {
            int y = __shfl_up_sync(0xffffffffu, xinc, off);
            if (lane >= off) xinc += y;
        }
        __shared__ int wsum[4];
        if (lane == 31) wsum[wid] = xinc;
        __syncthreads();
        int add = 0;
        for (int w = 0; w < wid; w++) add += wsum[w];
        int run = add + xinc - s;
        for (int i = begin; i < end; i++) { g_nstart[i] = run; run += g_Dn[i]; }
    } else {
        int h = blockIdx.x - 1;
        int s = g_hstart[h];
        int cnt = g_hstart[h + 1] - s;
        float s0 = 0.f, s1 = 0.f;
        for (int i = threadIdx.x; i < cnt; i += 128) {
            int n = node_idx[s + i];
            float2 d = *(const float2*)(g_d2 + 2 * n);
            s0 += d.x; s1 += d.y;
        }
#pragma unroll
        for (int off = 16; off >= 1; off >>= 1) {
            s0 += __shfl_xor_sync(0xffffffffu, s0, off);
            s1 += __shfl_xor_sync(0xffffffffu, s1, off);
        }
        __shared__ float r0[4], r1[4];
        int lane = threadIdx.x & 31, wid = threadIdx.x >> 5;
        if (lane == 0) { r0[wid] = s0; r1[wid] = s1; }
        __syncthreads();
        if (threadIdx.x == 0) {
            g_aedge[2 * h]     = r0[0] + r0[1] + r0[2] + r0[3];
            g_aedge[2 * h + 1] = r1[0] + r1[1] + r1[2] + r1[3];
        }
    }
}

// ---------------------------------------------------------------------------
// K4: counting-sort scatter: node-sorted list of hyperedge ids
// ---------------------------------------------------------------------------
__global__ void k_scatter(const int* __restrict__ node_idx,
                          const int* __restrict__ hedge_idx) {
    int e = blockIdx.x * blockDim.x + threadIdx.x;
    if (e >= EE) return;
    int n = node_idx[e];
    int pos = g_nstart[n] + atomicAdd(&g_cursor[n], 1);
    g_sh[pos] = hedge_idx[e];
}

// ---------------------------------------------------------------------------
// K5: per-node softmax stats (max + 1/denom), warp per node
// ---------------------------------------------------------------------------
__global__ void k_stats() {
    int gw   = (blockIdx.x * blockDim.x + threadIdx.x) >> 5;
    int lane = threadIdx.x & 31;
    if (gw >= NN) return;
    int n = gw, deg = g_Dn[n];
    if (deg == 0) return;
    int start = g_nstart[n];
    float2 d1p = *(const float2*)(g_d1 + 2 * n);

    float m0, m1, s0, s1;
    if (deg <= 32) {
        float v0 = -1e30f, v1 = -1e30f;
        if (lane < deg) {
            int h = g_sh[start + lane];
            float2 ae = *(const float2*)(g_aedge + 2 * h);
            v0 = d1p.x + ae.x; v0 = (v0 >= 0.f) ? v0 : 0.2f * v0;
            v1 = d1p.y + ae.y; v1 = (v1 >= 0.f) ? v1 : 0.2f * v1;
        }
        m0 = v0; m1 = v1;
#pragma unroll
        for (int off = 16; off >= 1; off >>= 1) {
            m0 = fmaxf(m0, __shfl_xor_sync(0xffffffffu, m0, off));
            m1 = fmaxf(m1, __shfl_xor_sync(0xffffffffu, m1, off));
        }
        s0 = (lane < deg) ? __expf(v0 - m0) : 0.f;
        s1 = (lane < deg) ? __expf(v1 - m1) : 0.f;
#pragma unroll
        for (int off = 16; off >= 1; off >>= 1) {
            s0 += __shfl_xor_sync(0xffffffffu, s0, off);
            s1 += __shfl_xor_sync(0xffffffffu, s1, off);
        }
    } else {
        m0 = -1e30f; m1 = -1e30f;
        for (int j = lane; j < deg; j += 32) {
            int h = g_sh[start + j];
            float2 ae = *(const float2*)(g_aedge + 2 * h);
            float v0 = d1p.x + ae.x; v0 = (v0 >= 0.f) ? v0 : 0.2f * v0;
            float v1 = d1p.y + ae.y; v1 = (v1 >= 0.f) ? v1 : 0.2f * v1;
            m0 = fmaxf(m0, v0); m1 = fmaxf(m1, v1);
        }
#pragma unroll
        for (int off = 16; off >= 1; off >>= 1) {
            m0 = fmaxf(m0, __shfl_xor_sync(0xffffffffu, m0, off));
            m1 = fmaxf(m1, __shfl_xor_sync(0xffffffffu, m1, off));
        }
        s0 = 0.f; s1 = 0.f;
        for (int j = lane; j < deg; j += 32) {
            int h = g_sh[start + j];
            float2 ae = *(const float2*)(g_aedge + 2 * h);
            float v0 = d1p.x + ae.x; v0 = (v0 >= 0.f) ? v0 : 0.2f * v0;
            float v1 = d1p.y + ae.y; v1 = (v1 >= 0.f) ? v1 : 0.2f * v1;
            s0 += __expf(v0 - m0); s1 += __expf(v1 - m1);
        }
#pragma unroll
        for (int off = 16; off >= 1; off >>= 1) {
            s0 += __shfl_xor_sync(0xffffffffu, s0, off);
            s1 += __shfl_xor_sync(0xffffffffu, s1, off);
        }
    }
    if (lane == 0) {
        *(float4*)(g_ni + n * 8)     = make_float4(d1p.x, d1p.y, m0, m1);
        *(float4*)(g_ni + n * 8 + 4) = make_float4(1.f / s0, 1.f / s1, (float)deg, 0.f);
    }
}

// ---------------------------------------------------------------------------
// K6: pass1 pre-projection: agg[h] = (1/cnt) * sum alpha_e * x_fp16[n_e]
//     (alpha recomputed inline; block per hyperedge, 128 threads = B*C)
// ---------------------------------------------------------------------------
__global__ void k_pass1(const int* __restrict__ node_idx) {
    int h = blockIdx.x;
    int s = g_hstart[h];
    int cnt = g_hstart[h + 1] - s;
    int t = threadIdx.x;
    int b = t >> 6;
    if (cnt == 0) { g_agg[(size_t)h * 128 + t] = 0.f; return; }
    float2 ae = *(const float2*)(g_aedge + 2 * h);

    __shared__ int   sn[128];
    __shared__ float sa0[128], sa1[128];
    float acc = 0.f;
    for (int base = 0; base < cnt; base += 128) {
        int mlen = min(128, cnt - base);
        __syncthreads();
        if (t < mlen) {
            int n = node_idx[s + base + t];
            float4 na = *(const float4*)(g_ni + n * 8);
            float4 nb = *(const float4*)(g_ni + n * 8 + 4);
            float v0 = na.x + ae.x; v0 = (v0 >= 0.f) ? v0 : 0.2f * v0;
            float v1 = na.y + ae.y; v1 = (v1 >= 0.f) ? v1 : 0.2f * v1;
            sn[t]  = n;
            sa0[t] = __expf(v0 - na.z) * nb.x;
            sa1[t] = __expf(v1 - na.w) * nb.y;
        }
        __syncthreads();
        const float* sa = b ? sa1 : sa0;
#pragma unroll 4
        for (int i = 0; i < mlen; i++)
            acc += sa[i] * __half2float(g_xh[(size_t)sn[i] * 128 + t]);
    }
    g_agg[(size_t)h * 128 + t] = acc * (1.0f / (float)cnt);
}

// ---------------------------------------------------------------------------
// K7: tiny GEMM  m = agg @ W  ([10000,64]@[64,64]) -> fp16
// ---------------------------------------------------------------------------
__global__ void k_m(const float* __restrict__ W) {
    __shared__ float Ws[64 * 64];
    __shared__ float As[64 * 68];
    int t = threadIdx.x;
    for (int i = t; i < 1024; i += 256)
        ((float4*)Ws)[i] = ((const float4*)W)[i];

    int r0base = blockIdx.x * 64;
#pragma unroll
    for (int k = 0; k < 4; k++) {
        int j = t + k * 256;            // float4 index, < 1024
        int rl = j >> 4, q = j & 15;
        int r = r0base + rl;
        float4 v = make_float4(0.f, 0.f, 0.f, 0.f);
        if (r < RH) v = *(const float4*)(g_agg + (size_t)r * 64 + q * 4);
        *(float4*)(As + rl * 68 + q * 4) = v;
    }
    __syncthreads();

    int rl0 = (t >> 4) * 4;
    int d0  = (t & 15) * 4;
    float4 acc0 = make_float4(0,0,0,0), acc1 = acc0, acc2 = acc0, acc3 = acc0;
#pragma unroll
    for (int k = 0; k < 64; k++) {
        float4 w = *(const float4*)(Ws + k * 64 + d0);
        float x0 = As[(rl0 + 0) * 68 + k];
        float x1 = As[(rl0 + 1) * 68 + k];
        float x2 = As[(rl0 + 2) * 68 + k];
        float x3 = As[(rl0 + 3) * 68 + k];
        acc0.x += x0*w.x; acc0.y += x0*w.y; acc0.z += x0*w.z; acc0.w += x0*w.w;
        acc1.x += x1*w.x; acc1.y += x1*w.y; acc1.z += x1*w.z; acc1.w += x1*w.w;
        acc2.x += x2*w.x; acc2.y += x2*w.y; acc2.z += x2*w.z; acc2.w += x2*w.w;
        acc3.x += x3*w.x; acc3.y += x3*w.y; acc3.z += x3*w.z; acc3.w += x3*w.w;
    }
    float4 accs[4] = {acc0, acc1, acc2, acc3};
#pragma unroll
    for (int i = 0; i < 4; i++) {
        int r = r0base + rl0 + i;
        if (r < RH) {
            *(__half2*)(g_mh + (size_t)r * 64 + d0)     = __floats2half2_rn(accs[i].x, accs[i].y);
            *(__half2*)(g_mh + (size_t)r * 64 + d0 + 2) = __floats2half2_rn(accs[i].z, accs[i].w);
        }
    }
}

// ---------------------------------------------------------------------------
// K8: pass2: out[b][n][c] = deg * sum alpha_e * m_fp16[h_e]  (warp per node)
// ---------------------------------------------------------------------------
__global__ void k_pass2(float* __restrict__ out) {
    int gw   = (blockIdx.x * blockDim.x + threadIdx.x) >> 5;
    int lane = threadIdx.x & 31;
    if (gw >= NN) return;
    int n = gw, deg = g_Dn[n];
    int start = g_nstart[n];
    float4 na = *(const float4*)(g_ni + n * 8);
    float4 nb = *(const float4*)(g_ni + n * 8 + 4);
    int moff = (lane >> 4) * 64 + (lane & 15) * 4;
    float4 acc = make_float4(0.f, 0.f, 0.f, 0.f);

    for (int base = 0; base < deg; base += 32) {
        int cnt = min(32, deg - base);
        int h = 0; float a0 = 0.f, a1 = 0.f;
        if (lane < cnt) {
            h = g_sh[start + base + lane];
            float2 ae = *(const float2*)(g_aedge + 2 * h);
            float v0 = na.x + ae.x; v0 = (v0 >= 0.f) ? v0 : 0.2f * v0;
            float v1 = na.y + ae.y; v1 = (v1 >= 0.f) ? v1 : 0.2f * v1;
            a0 = __expf(v0 - na.z) * nb.x;
            a1 = __expf(v1 - na.w) * nb.y;
        }
        for (int i = 0; i < cnt; i++) {
            int   hh  = __shfl_sync(0xffffffffu, h,  i);
            float aa0 = __shfl_sync(0xffffffffu, a0, i);
            float aa1 = __shfl_sync(0xffffffffu, a1, i);
            float aa  = (lane < 16) ? aa0 : aa1;
            uint2 raw = *(const uint2*)(g_mh + (size_t)hh * 128 + moff);
            float2 u = __half22float2(*(const __half2*)&raw.x);
            float2 v = __half22float2(*(const __half2*)&raw.y);
            acc.x += aa * u.x; acc.y += aa * u.y;
            acc.z += aa * v.x; acc.w += aa * v.y;
        }
    }
    float dn = (float)deg;
    int b  = lane >> 4;
    int c0 = (lane & 15) * 4;
    float4 o = make_float4(dn * acc.x, dn * acc.y, dn * acc.z, dn * acc.w);
    *(float4*)(out + (size_t)b * NN * 64 + (size_t)n * 64 + c0) = o;
}

// ---------------------------------------------------------------------------
// Launch
// ---------------------------------------------------------------------------
extern "C" void kernel_launch(void* const* d_in, const int* in_sizes, int n_in,
                              void* d_out, int out_size) {
    const float* x         = (const float*)d_in[0];   // [B,N,C]
    const float* weight    = (const float*)d_in[1];   // [C,C]
    const float* att       = (const float*)d_in[2];   // [2C]
    const int*   node_idx  = (const int*)d_in[3];     // [E]
    const int*   hedge_idx = (const int*)d_in[4];     // [E] sorted
    float*       out       = (float*)d_out;           // [B,N,C]

    k_init<<<197, 256>>>(weight, att);
    k_prep_deg<<<PREP_BLOCKS + (EE + 255) / 256, 256>>>(x, node_idx, hedge_idx);
    k_scan_aedge<<<HH + 1, 128>>>(node_idx);
    k_scatter<<<(EE + 255) / 256, 256>>>(node_idx, hedge_idx);
    k_stats<<<(NN * 32 + 255) / 256, 256>>>();
    k_pass1<<<HH, 128>>>(node_idx);
    k_m<<<(RH + 63) / 64, 256>>>(weight);
    k_pass2<<<(NN * 32 + 255) / 256, 256>>>(out);
}

// round 12
// speedup vs baseline: 1.6315x; 1.2645x over previous
#include <cuda_runtime.h>
#include <cuda_fp16.h>

// Problem constants (fixed by the dataset)
#define NN 50000      // nodes
#define HH 5000       // hyperedges
#define EE 400000     // incidence entries
#define RR (NN*2)     // (n,b) rows, r = 2n+b

#define DEG_BLOCKS 1563   // ceil(EE/256)
#define PREP_BLOCKS 12500 // RR/8 rows, 8 warps per block
#define SCHUNK 49         // scan chunk: 1024*49 >= NN

// ---------------------------------------------------------------------------
// Scratch (__device__ globals; zero-initialized at load; self-resetting)
// ---------------------------------------------------------------------------
__device__ __align__(16) __half g_xh[RR * 64];   // fp16 x, row r=2n+b (12.8 MB)
__device__ __align__(16) float  g_d1[RR];        // x . (W@att1)
__device__ __align__(16) float  g_d2[RR];        // x . (W@att2)
__device__ __align__(16) float  g_w[128];        // w1[64], w2[64]
__device__ volatile int g_wflag;                 // w ready flag (never reset; benign)
__device__ int   g_Dn[NN];                       // node degree (reset in pass2)
__device__ int   g_nstart[NN];                   // node segment starts
__device__ int   g_cursor[NN];                   // scatter cursors (reset by last-arriver)
__device__ int   g_done[NN];                     // completion counts (reset by last-arriver)
__device__ int   g_hstart[HH + 1];               // hyperedge segment starts (+sentinel)
__device__ __align__(16) float  g_aedge[HH * 2]; // per-hyperedge attention scalar
__device__ int   g_sh[EE];                       // hyperedge id per node-sorted slot
__device__ __align__(16) float  g_ni[NN * 8];    // per-node {d1_0,d1_1,mx0,mx1,inv0,inv1,deg,-}
__device__ __align__(16) __half g_mh[HH * 128];  // projected messages m (fp16)

// ---------------------------------------------------------------------------
// K1: block 0        -> g_w = {W@att1, W@att2}, then release flag
//     blocks 1..1563 -> node degrees (atomic) + hstart boundary fill
//     blocks 1564..  -> per-row d1,d2 + fp16 quantize of x (spin on flag)
// ---------------------------------------------------------------------------
__global__ void k1_prep(const float* __restrict__ x,
                        const float* __restrict__ W,
                        const float* __restrict__ att,
                        const int* __restrict__ node_idx,
                        const int* __restrict__ hedge_idx) {
    int b = blockIdx.x, t = threadIdx.x;
    if (b == 0) {
        if (t < 128) {
            int d = t & 63;
            const float* a = att + (t >> 6) * 64;
            float s = 0.f;
#pragma unroll
            for (int c = 0; c < 64; c++) s += W[d * 64 + c] * a[c];  // row d of W
            g_w[t] = s;
        }
        __syncthreads();
        __threadfence();
        if (t == 0) g_wflag = 1;
    } else if (b <= DEG_BLOCKS) {
        int e = (b - 1) * 256 + t;
        if (e >= EE) return;
        atomicAdd(&g_Dn[node_idx[e]], 1);
        int h  = hedge_idx[e];
        int hp = (e == 0) ? -1 : hedge_idx[e - 1];
        if (h != hp)
            for (int g = hp + 1; g <= h; g++) g_hstart[g] = e;
        if (e == EE - 1)
            for (int g = h + 1; g <= HH; g++) g_hstart[g] = EE;
    } else {
        if (t == 0) { while (g_wflag == 0) __nanosleep(64); }
        __syncthreads();            // block-wide fence: g_w visible after flag
        int warp = t >> 5, lane = t & 31;
        int r = (b - (DEG_BLOCKS + 1)) * 8 + warp;   // < RR always
        int n = r >> 1, bb = r & 1;
        float2 xv = *(const float2*)(x + (size_t)bb * NN * 64 + (size_t)n * 64 + lane * 2);
        float2 w1 = *(const float2*)(g_w + 2 * lane);
        float2 w2 = *(const float2*)(g_w + 64 + 2 * lane);
        float p1 = xv.x * w1.x + xv.y * w1.y;
        float p2 = xv.x * w2.x + xv.y * w2.y;
#pragma unroll
        for (int off = 16; off >= 1; off >>= 1) {
            p1 += __shfl_xor_sync(0xffffffffu, p1, off);
            p2 += __shfl_xor_sync(0xffffffffu, p2, off);
        }
        if (lane == 0) { g_d1[r] = p1; g_d2[r] = p2; }
        *(__half2*)(g_xh + (size_t)r * 64 + lane * 2) = __floats2half2_rn(xv.x, xv.y);
    }
}

// ---------------------------------------------------------------------------
// K2: block 0 (1024 thr) = exclusive scan of Dn -> nstart (49 elems/thread)
//     blocks 1..625      = 8 hyperedges each: aedge[h][b] = sum d2[2n+b]
// ---------------------------------------------------------------------------
__global__ void k2_scan_aedge(const int* __restrict__ node_idx) {
    int t = threadIdx.x;
    if (blockIdx.x == 0) {
        int begin = t * SCHUNK;
        int end   = min(begin + SCHUNK, NN);
        int s = 0;
        for (int i = begin; i < end; i++) s += g_Dn[i];
        int lane = t & 31, wid = t >> 5;
        int inc = s;
#pragma unroll
        for (int off = 1; off < 32; off <<= 1) {
            int y = __shfl_up_sync(0xffffffffu, inc, off);
            if (lane >= off) inc += y;
        }
        __shared__ int ws[32];
        if (lane == 31) ws[wid] = inc;
        __syncthreads();
        if (wid == 0) {
            int v = ws[lane];
#pragma unroll
            for (int off = 1; off < 32; off <<= 1) {
                int y = __shfl_up_sync(0xffffffffu, v, off);
                if (lane >= off) v += y;
            }
            ws[lane] = v;
        }
        __syncthreads();
        int run = inc - s + ((wid > 0) ? ws[wid - 1] : 0);
        for (int i = begin; i < end; i++) { g_nstart[i] = run; run += g_Dn[i]; }
    } else {
        int g  = t >> 7;            // group 0..7, 128 threads each
        int gt = t & 127;
        int h  = (blockIdx.x - 1) * 8 + g;    // < 5000 exactly (625*8)
        int s  = g_hstart[h];
        int cnt = g_hstart[h + 1] - s;
        float s0 = 0.f, s1 = 0.f;
        for (int i = gt; i < cnt; i += 128) {
            int n = node_idx[s + i];
            float2 d = *(const float2*)(g_d2 + 2 * n);
            s0 += d.x; s1 += d.y;
        }
#pragma unroll
        for (int off = 16; off >= 1; off >>= 1) {
            s0 += __shfl_xor_sync(0xffffffffu, s0, off);
            s1 += __shfl_xor_sync(0xffffffffu, s1, off);
        }
        __shared__ float r0[8][4], r1[8][4];
        int lane = gt & 31, wig = gt >> 5;
        if (lane == 0) { r0[g][wig] = s0; r1[g][wig] = s1; }
        __syncthreads();
        if (gt == 0) {
            g_aedge[2 * h]     = r0[g][0] + r0[g][1] + r0[g][2] + r0[g][3];
            g_aedge[2 * h + 1] = r1[g][0] + r1[g][1] + r1[g][2] + r1[g][3];
        }
    }
}

// ---------------------------------------------------------------------------
// K3: counting-sort scatter + last-arriver computes per-node softmax stats
//     (online max/denom), and resets cursor/done for the next replay.
// ---------------------------------------------------------------------------
__global__ void k3_scatter_stats(const int* __restrict__ node_idx,
                                 const int* __restrict__ hedge_idx) {
    int e = blockIdx.x * 256 + threadIdx.x;
    if (e >= EE) return;
    int n = node_idx[e], h = hedge_idx[e];
    int pos = g_nstart[n] + atomicAdd(&g_cursor[n], 1);
    g_sh[pos] = h;
    __threadfence();
    int deg = g_Dn[n];
    if (atomicAdd(&g_done[n], 1) == deg - 1) {
        __threadfence();
        g_cursor[n] = 0; g_done[n] = 0;       // self-reset (no more writers for n)
        int start = g_nstart[n];
        float d10 = g_d1[2 * n], d11 = g_d1[2 * n + 1];
        float m0 = -1e30f, m1 = -1e30f, s0 = 0.f, s1 = 0.f;
        for (int j = 0; j < deg; j++) {
            int hh = g_sh[start + j];
            float2 ae = *(const float2*)(g_aedge + 2 * hh);
            float v0 = d10 + ae.x; v0 = (v0 >= 0.f) ? v0 : 0.2f * v0;
            float v1 = d11 + ae.y; v1 = (v1 >= 0.f) ? v1 : 0.2f * v1;
            if (v0 > m0) { s0 = s0 * __expf(m0 - v0) + 1.f; m0 = v0; }
            else         { s0 += __expf(v0 - m0); }
            if (v1 > m1) { s1 = s1 * __expf(m1 - v1) + 1.f; m1 = v1; }
            else         { s1 += __expf(v1 - m1); }
        }
        *(float4*)(g_ni + n * 8)     = make_float4(d10, d11, m0, m1);
        *(float4*)(g_ni + n * 8 + 4) = make_float4(1.f / s0, 1.f / s1, (float)deg, 0.f);
    }
}

// ---------------------------------------------------------------------------
// K4: pass1 + projection fused (block per hyperedge, 128 threads = B*C):
//     agg = (1/cnt) * sum alpha_e * x_fp16[n_e];  m = agg @ W  -> g_mh (fp16)
//     W read via __ldg: L1-persistent within launch (~16KB/SM total)
// ---------------------------------------------------------------------------
__global__ void k4_pass1m(const int* __restrict__ node_idx,
                          const float* __restrict__ W) {
    int h = blockIdx.x, t = threadIdx.x;
    int s = g_hstart[h];
    int cnt = g_hstart[h + 1] - s;
    if (cnt == 0) { g_mh[h * 128 + t] = __float2half(0.f); return; }
    float2 ae = *(const float2*)(g_aedge + 2 * h);
    int b = t >> 6;

    __shared__ int   sn[128];
    __shared__ float sa0[128], sa1[128];
    __shared__ float sA[128];
    float acc = 0.f;
    for (int base = 0; base < cnt; base += 128) {
        int mlen = min(128, cnt - base);
        __syncthreads();
        if (t < mlen) {
            int n = node_idx[s + base + t];
            float4 na = *(const float4*)(g_ni + n * 8);
            float4 nb = *(const float4*)(g_ni + n * 8 + 4);
            float v0 = na.x + ae.x; v0 = (v0 >= 0.f) ? v0 : 0.2f * v0;
            float v1 = na.y + ae.y; v1 = (v1 >= 0.f) ? v1 : 0.2f * v1;
            sn[t]  = n;
            sa0[t] = __expf(v0 - na.z) * nb.x;
            sa1[t] = __expf(v1 - na.w) * nb.y;
        }
        __syncthreads();
        const float* sa = b ? sa1 : sa0;
#pragma unroll 4
        for (int i = 0; i < mlen; i++)
            acc += sa[i] * __half2float(g_xh[(size_t)sn[i] * 128 + t]);
    }
    sA[t] = acc * (1.0f / (float)cnt);
    __syncthreads();
    // projection: thread t = (b, d); m[b][d] = sum_c agg[b][c] * W[c][d]
    int d = t & 63;
    const float* arow = sA + b * 64;
    float m = 0.f;
#pragma unroll 8
    for (int c = 0; c < 64; c++)
        m += arow[c] * __ldg(W + c * 64 + d);
    g_mh[h * 128 + t] = __float2half(m);
}

// ---------------------------------------------------------------------------
// K5: pass2: out[b][n][c] = deg * sum alpha_e * m_fp16[h_e] (warp per node)
//     also resets g_Dn for the next replay.
// ---------------------------------------------------------------------------
__global__ void k5_pass2(float* __restrict__ out) {
    int gw   = (blockIdx.x * blockDim.x + threadIdx.x) >> 5;
    int lane = threadIdx.x & 31;
    if (gw >= NN) return;
    int n = gw, deg = g_Dn[n];
    int start = g_nstart[n];
    float4 na = *(const float4*)(g_ni + n * 8);
    float4 nb = *(const float4*)(g_ni + n * 8 + 4);
    int moff = (lane >> 4) * 64 + (lane & 15) * 4;
    float4 acc = make_float4(0.f, 0.f, 0.f, 0.f);

    for (int base = 0; base < deg; base += 32) {
        int cnt = min(32, deg - base);
        int h = 0; float a0 = 0.f, a1 = 0.f;
        if (lane < cnt) {
            h = g_sh[start + base + lane];
            float2 ae = *(const float2*)(g_aedge + 2 * h);
            float v0 = na.x + ae.x; v0 = (v0 >= 0.f) ? v0 : 0.2f * v0;
            float v1 = na.y + ae.y; v1 = (v1 >= 0.f) ? v1 : 0.2f * v1;
            a0 = __expf(v0 - na.z) * nb.x;
            a1 = __expf(v1 - na.w) * nb.y;
        }
        for (int i = 0; i < cnt; i++) {
            int   hh  = __shfl_sync(0xffffffffu, h,  i);
            float aa0 = __shfl_sync(0xffffffffu, a0, i);
            float aa1 = __shfl_sync(0xffffffffu, a1, i);
            float aa  = (lane < 16) ? aa0 : aa1;
            uint2 raw = *(const uint2*)(g_mh + (size_t)hh * 128 + moff);
            float2 u = __half22float2(*(const __half2*)&raw.x);
            float2 v = __half22float2(*(const __half2*)&raw.y);
            acc.x += aa * u.x; acc.y += aa * u.y;
            acc.z += aa * v.x; acc.w += aa * v.y;
        }
    }
    if (lane == 0) g_Dn[n] = 0;       // self-reset for next replay
    float dn = (float)deg;
    int b  = lane >> 4;
    int c0 = (lane & 15) * 4;
    float4 o = make_float4(dn * acc.x, dn * acc.y, dn * acc.z, dn * acc.w);
    *(float4*)(out + (size_t)b * NN * 64 + (size_t)n * 64 + c0) = o;
}

// ---------------------------------------------------------------------------
// Launch: 5 kernels
// ---------------------------------------------------------------------------
extern "C" void kernel_launch(void* const* d_in, const int* in_sizes, int n_in,
                              void* d_out, int out_size) {
    const float* x         = (const float*)d_in[0];   // [B,N,C]
    const float* weight    = (const float*)d_in[1];   // [C,C]
    const float* att       = (const float*)d_in[2];   // [2C]
    const int*   node_idx  = (const int*)d_in[3];     // [E]
    const int*   hedge_idx = (const int*)d_in[4];     // [E] sorted
    float*       out       = (float*)d_out;           // [B,N,C]

    k1_prep<<<1 + DEG_BLOCKS + PREP_BLOCKS, 256>>>(x, weight, att, node_idx, hedge_idx);
    k2_scan_aedge<<<626, 1024>>>(node_idx);
    k3_scatter_stats<<<DEG_BLOCKS, 256>>>(node_idx, hedge_idx);
    k4_pass1m<<<HH, 128>>>(node_idx, weight);
    k5_pass2<<<(NN * 32 + 255) / 256, 256>>>(out);
}

// round 13
// speedup vs baseline: 1.8822x; 1.1537x over previous
#include <cuda_runtime.h>
#include <cuda_fp16.h>

// Problem constants (fixed by the dataset)
#define NN 50000      // nodes
#define HH 5000       // hyperedges
#define EE 400000     // incidence entries
#define RR (NN*2)     // (n,b) rows, r = 2n+b

#define DEG_BLOCKS 1563   // ceil(EE/256)
#define PREP_BLOCKS 12500 // RR/8 rows, 8 warps per block
#define SCHUNK 49         // scan chunk: 1024*49 >= NN

// ---------------------------------------------------------------------------
// Scratch (__device__ globals; zero-initialized at load; self-resetting)
// ---------------------------------------------------------------------------
__device__ __align__(16) __half g_xh[RR * 64];   // fp16 x, row r=2n+b (12.8 MB)
__device__ __align__(16) float  g_d1[RR];        // x . (W@att1)
__device__ __align__(16) float  g_d2[RR];        // x . (W@att2)
__device__ __align__(16) float  g_w[128];        // w1[64], w2[64]
__device__ volatile int g_wflag;                 // w ready flag (never reset; benign)
__device__ int   g_Dn[NN];                       // node degree (reset in pass2)
__device__ int   g_nstart[NN];                   // node segment starts
__device__ int   g_cursor[NN];                   // scatter cursors (reset by last-arriver)
__device__ int   g_done[NN];                     // completion counts (reset by last-arriver)
__device__ int   g_hstart[HH + 1];               // hyperedge segment starts (+sentinel)
__device__ __align__(16) float  g_aedge[HH * 2]; // per-hyperedge attention scalar
__device__ int   g_sh[EE];                       // hyperedge id per node-sorted slot
__device__ __align__(16) float  g_ni[NN * 8];    // per-node {d1_0,d1_1,mx0,mx1,inv0,inv1,deg,-}
__device__ __align__(16) __half g_mh[HH * 128];  // projected messages m (fp16)

// ---------------------------------------------------------------------------
// K1: block 0        -> g_w = {W@att1, W@att2}, then release flag
//     blocks 1..1563 -> node degrees (atomic) + hstart boundary fill
//     blocks 1564..  -> per-row d1,d2 + fp16 quantize of x (spin on flag)
// ---------------------------------------------------------------------------
__global__ void k1_prep(const float* __restrict__ x,
                        const float* __restrict__ W,
                        const float* __restrict__ att,
                        const int* __restrict__ node_idx,
                        const int* __restrict__ hedge_idx) {
    int b = blockIdx.x, t = threadIdx.x;
    if (b == 0) {
        if (t < 128) {
            int d = t & 63;
            const float* a = att + (t >> 6) * 64;
            float s = 0.f;
#pragma unroll
            for (int c = 0; c < 64; c++) s += W[d * 64 + c] * a[c];  // row d of W
            g_w[t] = s;
        }
        __syncthreads();
        __threadfence();
        if (t == 0) g_wflag = 1;
    } else if (b <= DEG_BLOCKS) {
        int e = (b - 1) * 256 + t;
        if (e >= EE) return;
        atomicAdd(&g_Dn[node_idx[e]], 1);
        int h  = hedge_idx[e];
        int hp = (e == 0) ? -1 : hedge_idx[e - 1];
        if (h != hp)
            for (int g = hp + 1; g <= h; g++) g_hstart[g] = e;
        if (e == EE - 1)
            for (int g = h + 1; g <= HH; g++) g_hstart[g] = EE;
    } else {
        if (t == 0) { while (g_wflag == 0) __nanosleep(64); }
        __syncthreads();            // block-wide fence: g_w visible after flag
        int warp = t >> 5, lane = t & 31;
        int r = (b - (DEG_BLOCKS + 1)) * 8 + warp;   // < RR always
        int n = r >> 1, bb = r & 1;
        float2 xv = *(const float2*)(x + (size_t)bb * NN * 64 + (size_t)n * 64 + lane * 2);
        float2 w1 = *(const float2*)(g_w + 2 * lane);
        float2 w2 = *(const float2*)(g_w + 64 + 2 * lane);
        float p1 = xv.x * w1.x + xv.y * w1.y;
        float p2 = xv.x * w2.x + xv.y * w2.y;
#pragma unroll
        for (int off = 16; off >= 1; off >>= 1) {
            p1 += __shfl_xor_sync(0xffffffffu, p1, off);
            p2 += __shfl_xor_sync(0xffffffffu, p2, off);
        }
        if (lane == 0) { g_d1[r] = p1; g_d2[r] = p2; }
        *(__half2*)(g_xh + (size_t)r * 64 + lane * 2) = __floats2half2_rn(xv.x, xv.y);
    }
}

// ---------------------------------------------------------------------------
// K2: block 0 (1024 thr) = exclusive scan of Dn -> nstart (49 elems/thread)
//     blocks 1..625      = 8 hyperedges each: aedge[h][b] = sum d2[2n+b]
// ---------------------------------------------------------------------------
__global__ void k2_scan_aedge(const int* __restrict__ node_idx) {
    int t = threadIdx.x;
    if (blockIdx.x == 0) {
        int begin = t * SCHUNK;
        int end   = min(begin + SCHUNK, NN);
        int s = 0;
        for (int i = begin; i < end; i++) s += g_Dn[i];
        int lane = t & 31, wid = t >> 5;
        int inc = s;
#pragma unroll
        for (int off = 1; off < 32; off <<= 1) {
            int y = __shfl_up_sync(0xffffffffu, inc, off);
            if (lane >= off) inc += y;
        }
        __shared__ int ws[32];
        if (lane == 31) ws[wid] = inc;
        __syncthreads();
        if (wid == 0) {
            int v = ws[lane];
#pragma unroll
            for (int off = 1; off < 32; off <<= 1) {
                int y = __shfl_up_sync(0xffffffffu, v, off);
                if (lane >= off) v += y;
            }
            ws[lane] = v;
        }
        __syncthreads();
        int run = inc - s + ((wid > 0) ? ws[wid - 1] : 0);
        for (int i = begin; i < end; i++) { g_nstart[i] = run; run += g_Dn[i]; }
    } else {
        int g  = t >> 7;            // group 0..7, 128 threads each
        int gt = t & 127;
        int h  = (blockIdx.x - 1) * 8 + g;    // < 5000 exactly (625*8)
        int s  = g_hstart[h];
        int cnt = g_hstart[h + 1] - s;
        float s0 = 0.f, s1 = 0.f;
        for (int i = gt; i < cnt; i += 128) {
            int n = node_idx[s + i];
            float2 d = *(const float2*)(g_d2 + 2 * n);
            s0 += d.x; s1 += d.y;
        }
#pragma unroll
        for (int off = 16; off >= 1; off >>= 1) {
            s0 += __shfl_xor_sync(0xffffffffu, s0, off);
            s1 += __shfl_xor_sync(0xffffffffu, s1, off);
        }
        __shared__ float r0[8][4], r1[8][4];
        int lane = gt & 31, wig = gt >> 5;
        if (lane == 0) { r0[g][wig] = s0; r1[g][wig] = s1; }
        __syncthreads();
        if (gt == 0) {
            g_aedge[2 * h]     = r0[g][0] + r0[g][1] + r0[g][2] + r0[g][3];
            g_aedge[2 * h + 1] = r1[g][0] + r1[g][1] + r1[g][2] + r1[g][3];
        }
    }
}

// ---------------------------------------------------------------------------
// K3: counting-sort scatter + last-arriver computes per-node softmax stats
//     (online max/denom), and resets cursor/done for the next replay.
// ---------------------------------------------------------------------------
__global__ void k3_scatter_stats(const int* __restrict__ node_idx,
                                 const int* __restrict__ hedge_idx) {
    int e = blockIdx.x * 256 + threadIdx.x;
    if (e >= EE) return;
    int n = node_idx[e], h = hedge_idx[e];
    int pos = g_nstart[n] + atomicAdd(&g_cursor[n], 1);
    g_sh[pos] = h;
    __threadfence();
    int deg = g_Dn[n];
    if (atomicAdd(&g_done[n], 1) == deg - 1) {
        __threadfence();
        g_cursor[n] = 0; g_done[n] = 0;       // self-reset (no more writers for n)
        int start = g_nstart[n];
        float d10 = g_d1[2 * n], d11 = g_d1[2 * n + 1];
        float m0 = -1e30f, m1 = -1e30f, s0 = 0.f, s1 = 0.f;
        for (int j = 0; j < deg; j++) {
            int hh = g_sh[start + j];
            float2 ae = *(const float2*)(g_aedge + 2 * hh);
            float v0 = d10 + ae.x; v0 = (v0 >= 0.f) ? v0 : 0.2f * v0;
            float v1 = d11 + ae.y; v1 = (v1 >= 0.f) ? v1 : 0.2f * v1;
            if (v0 > m0) { s0 = s0 * __expf(m0 - v0) + 1.f; m0 = v0; }
            else         { s0 += __expf(v0 - m0); }
            if (v1 > m1) { s1 = s1 * __expf(m1 - v1) + 1.f; m1 = v1; }
            else         { s1 += __expf(v1 - m1); }
        }
        *(float4*)(g_ni + n * 8)     = make_float4(d10, d11, m0, m1);
        *(float4*)(g_ni + n * 8 + 4) = make_float4(1.f / s0, 1.f / s1, (float)deg, 0.f);
    }
}

// ---------------------------------------------------------------------------
// K4: pass1 + projection fused (block per hyperedge, 128 threads):
//     4 groups x 32 lanes; each lane loads uint2 (4 halfs) so one warp covers
//     a full 256B node row in one LDG.64; 4 incidences per inner iteration.
//     agg = (1/cnt) * sum alpha_e * x_fp16[n_e];  m = agg @ W -> g_mh (fp16)
// ---------------------------------------------------------------------------
__global__ void k4_pass1m(const int* __restrict__ node_idx,
                          const float* __restrict__ W) {
    int h = blockIdx.x, t = threadIdx.x;
    int s = g_hstart[h];
    int cnt = g_hstart[h + 1] - s;
    if (cnt == 0) { g_mh[h * 128 + t] = __float2half(0.f); return; }
    float2 ae = *(const float2*)(g_aedge + 2 * h);

    int grp  = t >> 5;            // 0..3: which incidence within a quad
    int lane = t & 31;            // owns halfs [lane*4, lane*4+4) of the row
    int bsel = lane >> 4;         // batch of those 4 halfs

    __shared__ int   sn[128];
    __shared__ float sa[2][128];
    __shared__ __align__(16) float red[4][32][4];
    __shared__ float sA[128];

    float4 acc = make_float4(0.f, 0.f, 0.f, 0.f);
    for (int base = 0; base < cnt; base += 128) {
        int mlen = min(128, cnt - base);
        __syncthreads();
        if (t < mlen) {
            int n = node_idx[s + base + t];
            float4 na = *(const float4*)(g_ni + n * 8);
            float4 nb = *(const float4*)(g_ni + n * 8 + 4);
            float v0 = na.x + ae.x; v0 = (v0 >= 0.f) ? v0 : 0.2f * v0;
            float v1 = na.y + ae.y; v1 = (v1 >= 0.f) ? v1 : 0.2f * v1;
            sn[t]    = n;
            sa[0][t] = __expf(v0 - na.z) * nb.x;
            sa[1][t] = __expf(v1 - na.w) * nb.y;
        }
        __syncthreads();
        for (int i = grp; i < mlen; i += 4) {
            int n = sn[i];
            float a = sa[bsel][i];
            uint2 raw = *(const uint2*)(g_xh + (size_t)n * 128 + lane * 4);
            float2 u = __half22float2(*(const __half2*)&raw.x);
            float2 v = __half22float2(*(const __half2*)&raw.y);
            acc.x += a * u.x; acc.y += a * u.y;
            acc.z += a * v.x; acc.w += a * v.y;
        }
    }
    *(float4*)red[grp][lane] = acc;
    __syncthreads();
    if (grp == 0) {
        float4 r0 = *(float4*)red[0][lane];
        float4 r1 = *(float4*)red[1][lane];
        float4 r2 = *(float4*)red[2][lane];
        float4 r3 = *(float4*)red[3][lane];
        float inv = 1.0f / (float)cnt;
        sA[lane * 4 + 0] = (r0.x + r1.x + r2.x + r3.x) * inv;
        sA[lane * 4 + 1] = (r0.y + r1.y + r2.y + r3.y) * inv;
        sA[lane * 4 + 2] = (r0.z + r1.z + r2.z + r3.z) * inv;
        sA[lane * 4 + 3] = (r0.w + r1.w + r2.w + r3.w) * inv;
    }
    __syncthreads();
    // projection: thread t = (b, d); m[b][d] = sum_c agg[b][c] * W[c][d]
    int d = t & 63;
    const float* arow = sA + (t >> 6) * 64;
    float m = 0.f;
#pragma unroll 8
    for (int c = 0; c < 64; c++)
        m += arow[c] * __ldg(W + c * 64 + d);
    g_mh[h * 128 + t] = __float2half(m);
}

// ---------------------------------------------------------------------------
// K5: pass2: out[b][n][c] = deg * sum alpha_e * m_fp16[h_e] (warp per node)
//     h / alpha staged through per-warp smem (LDS broadcast, no SHFL chain);
//     also resets g_Dn for the next replay.
// ---------------------------------------------------------------------------
__global__ void k5_pass2(float* __restrict__ out) {
    int wip  = threadIdx.x >> 5;                       // warp in block (0..7)
    int gw   = (blockIdx.x * blockDim.x + threadIdx.x) >> 5;
    int lane = threadIdx.x & 31;
    __shared__ int    sh_h[8][32];
    __shared__ float2 sh_a[8][32];
    if (gw >= NN) return;
    int n = gw, deg = g_Dn[n];
    int start = g_nstart[n];
    float4 na = *(const float4*)(g_ni + n * 8);
    float4 nb = *(const float4*)(g_ni + n * 8 + 4);
    int moff = (lane >> 4) * 64 + (lane & 15) * 4;
    int asel = (lane >> 4);                            // which alpha component
    float4 acc = make_float4(0.f, 0.f, 0.f, 0.f);

    for (int base = 0; base < deg; base += 32) {
        int cnt = min(32, deg - base);
        if (lane < cnt) {
            int h = g_sh[start + base + lane];
            float2 aev = *(const float2*)(g_aedge + 2 * h);
            float v0 = na.x + aev.x; v0 = (v0 >= 0.f) ? v0 : 0.2f * v0;
            float v1 = na.y + aev.y; v1 = (v1 >= 0.f) ? v1 : 0.2f * v1;
            sh_h[wip][lane] = h;
            sh_a[wip][lane] = make_float2(__expf(v0 - na.z) * nb.x,
                                          __expf(v1 - na.w) * nb.y);
        }
        __syncwarp();
        for (int i = 0; i < cnt; i++) {
            int   hh = sh_h[wip][i];
            float aa = ((const float*)&sh_a[wip][i])[asel];
            uint2 raw = *(const uint2*)(g_mh + (size_t)hh * 128 + moff);
            float2 u = __half22float2(*(const __half2*)&raw.x);
            float2 v = __half22float2(*(const __half2*)&raw.y);
            acc.x += aa * u.x; acc.y += aa * u.y;
            acc.z += aa * v.x; acc.w += aa * v.y;
        }
        __syncwarp();
    }
    if (lane == 0) g_Dn[n] = 0;       // self-reset for next replay
    float dn = (float)deg;
    int b  = lane >> 4;
    int c0 = (lane & 15) * 4;
    float4 o = make_float4(dn * acc.x, dn * acc.y, dn * acc.z, dn * acc.w);
    *(float4*)(out + (size_t)b * NN * 64 + (size_t)n * 64 + c0) = o;
}

// ---------------------------------------------------------------------------
// Launch: 5 kernels
// ---------------------------------------------------------------------------
extern "C" void kernel_launch(void* const* d_in, const int* in_sizes, int n_in,
                              void* d_out, int out_size) {
    const float* x         = (const float*)d_in[0];   // [B,N,C]
    const float* weight    = (const float*)d_in[1];   // [C,C]
    const float* att       = (const float*)d_in[2];   // [2C]
    const int*   node_idx  = (const int*)d_in[3];     // [E]
    const int*   hedge_idx = (const int*)d_in[4];     // [E] sorted
    float*       out       = (float*)d_out;           // [B,N,C]

    k1_prep<<<1 + DEG_BLOCKS + PREP_BLOCKS, 256>>>(x, weight, att, node_idx, hedge_idx);
    k2_scan_aedge<<<626, 1024>>>(node_idx);
    k3_scatter_stats<<<DEG_BLOCKS, 256>>>(node_idx, hedge_idx);
    k4_pass1m<<<HH, 128>>>(node_idx, weight);
    k5_pass2<<<(NN * 32 + 255) / 256, 256>>>(out);
}

// round 14
// speedup vs baseline: 1.8836x; 1.0007x over previous
#include <cuda_runtime.h>
#include <cuda_fp16.h>

// Problem constants (fixed by the dataset)
#define NN 50000      // nodes
#define HH 5000       // hyperedges
#define EE 400000     // incidence entries
#define RR (NN*2)     // (n,b) rows, r = 2n+b

#define DEG_BLOCKS 1563   // ceil(EE/256)
#define PREP_BLOCKS 12500 // RR/8 rows, 8 warps per block
#define SCHUNK 49         // scan chunk: 1024*49 >= NN

// ---------------------------------------------------------------------------
// Scratch (__device__ globals; zero-initialized at load; self-resetting)
// ---------------------------------------------------------------------------
__device__ __align__(16) __half g_xh[RR * 64];   // fp16 x, row r=2n+b (12.8 MB)
__device__ __align__(16) float  g_d1[RR];        // x . (W@att1)
__device__ __align__(16) float  g_d2[RR];        // x . (W@att2)
__device__ __align__(16) float  g_w[128];        // w1[64], w2[64]
__device__ volatile int g_wflag;                 // w ready flag (never reset; benign)
__device__ int   g_Dn[NN];                       // node degree (reset in pass2)
__device__ int   g_nstart[NN];                   // node segment starts
__device__ int   g_cursor[NN];                   // scatter cursors (reset by last-arriver)
__device__ int   g_done[NN];                     // completion counts (reset by last-arriver)
__device__ int   g_hstart[HH + 1];               // hyperedge segment starts (+sentinel)
__device__ __align__(16) float  g_aedge[HH * 2]; // per-hyperedge attention scalar
__device__ int   g_sh[EE];                       // hyperedge id per node-sorted slot
__device__ __align__(16) float  g_ni[NN * 8];    // per-node {d1_0,d1_1,mx0,mx1,inv0,inv1,deg,-}
__device__ __align__(16) __half g_mh[HH * 128];  // projected messages m (fp16)

// ---------------------------------------------------------------------------
// K1: block 0        -> g_w = {W@att1, W@att2}, then release flag
//     blocks 1..1563 -> node degrees (atomic) + hstart boundary fill
//     blocks 1564..  -> per-row d1,d2 + fp16 quantize of x (spin on flag)
// ---------------------------------------------------------------------------
__global__ void k1_prep(const float* __restrict__ x,
                        const float* __restrict__ W,
                        const float* __restrict__ att,
                        const int* __restrict__ node_idx,
                        const int* __restrict__ hedge_idx) {
    int b = blockIdx.x, t = threadIdx.x;
    if (b == 0) {
        if (t < 128) {
            int d = t & 63;
            const float* a = att + (t >> 6) * 64;
            float s = 0.f;
#pragma unroll
            for (int c = 0; c < 64; c++) s += W[d * 64 + c] * a[c];  // row d of W
            g_w[t] = s;
        }
        __syncthreads();
        __threadfence();
        if (t == 0) g_wflag = 1;
    } else if (b <= DEG_BLOCKS) {
        int e = (b - 1) * 256 + t;
        if (e >= EE) return;
        atomicAdd(&g_Dn[node_idx[e]], 1);
        int h  = hedge_idx[e];
        int hp = (e == 0) ? -1 : hedge_idx[e - 1];
        if (h != hp)
            for (int g = hp + 1; g <= h; g++) g_hstart[g] = e;
        if (e == EE - 1)
            for (int g = h + 1; g <= HH; g++) g_hstart[g] = EE;
    } else {
        if (t == 0) { while (g_wflag == 0) __nanosleep(64); }
        __syncthreads();            // block-wide fence: g_w visible after flag
        int warp = t >> 5, lane = t & 31;
        int r = (b - (DEG_BLOCKS + 1)) * 8 + warp;   // < RR always
        int n = r >> 1, bb = r & 1;
        float2 xv = *(const float2*)(x + (size_t)bb * NN * 64 + (size_t)n * 64 + lane * 2);
        float2 w1 = *(const float2*)(g_w + 2 * lane);
        float2 w2 = *(const float2*)(g_w + 64 + 2 * lane);
        float p1 = xv.x * w1.x + xv.y * w1.y;
        float p2 = xv.x * w2.x + xv.y * w2.y;
#pragma unroll
        for (int off = 16; off >= 1; off >>= 1) {
            p1 += __shfl_xor_sync(0xffffffffu, p1, off);
            p2 += __shfl_xor_sync(0xffffffffu, p2, off);
        }
        if (lane == 0) { g_d1[r] = p1; g_d2[r] = p2; }
        *(__half2*)(g_xh + (size_t)r * 64 + lane * 2) = __floats2half2_rn(xv.x, xv.y);
    }
}

// ---------------------------------------------------------------------------
// K2: block 0 (1024 thr) = exclusive scan of Dn -> nstart (49 elems/thread)
//     blocks 1..625      = 8 hyperedges each: aedge[h][b] = sum d2[2n+b]
// ---------------------------------------------------------------------------
__global__ void k2_scan_aedge(const int* __restrict__ node_idx) {
    int t = threadIdx.x;
    if (blockIdx.x == 0) {
        int begin = t * SCHUNK;
        int end   = min(begin + SCHUNK, NN);
        int s = 0;
        for (int i = begin; i < end; i++) s += g_Dn[i];
        int lane = t & 31, wid = t >> 5;
        int inc = s;
#pragma unroll
        for (int off = 1; off < 32; off <<= 1) {
            int y = __shfl_up_sync(0xffffffffu, inc, off);
            if (lane >= off) inc += y;
        }
        __shared__ int ws[32];
        if (lane == 31) ws[wid] = inc;
        __syncthreads();
        if (wid == 0) {
            int v = ws[lane];
#pragma unroll
            for (int off = 1; off < 32; off <<= 1) {
                int y = __shfl_up_sync(0xffffffffu, v, off);
                if (lane >= off) v += y;
            }
            ws[lane] = v;
        }
        __syncthreads();
        int run = inc - s + ((wid > 0) ? ws[wid - 1] : 0);
        for (int i = begin; i < end; i++) { g_nstart[i] = run; run += g_Dn[i]; }
    } else {
        int g  = t >> 7;            // group 0..7, 128 threads each
        int gt = t & 127;
        int h  = (blockIdx.x - 1) * 8 + g;    // < 5000 exactly (625*8)
        int s  = g_hstart[h];
        int cnt = g_hstart[h + 1] - s;
        float s0 = 0.f, s1 = 0.f;
        for (int i = gt; i < cnt; i += 128) {
            int n = node_idx[s + i];
            float2 d = *(const float2*)(g_d2 + 2 * n);
            s0 += d.x; s1 += d.y;
        }
#pragma unroll
        for (int off = 16; off >= 1; off >>= 1) {
            s0 += __shfl_xor_sync(0xffffffffu, s0, off);
            s1 += __shfl_xor_sync(0xffffffffu, s1, off);
        }
        __shared__ float r0[8][4], r1[8][4];
        int lane = gt & 31, wig = gt >> 5;
        if (lane == 0) { r0[g][wig] = s0; r1[g][wig] = s1; }
        __syncthreads();
        if (gt == 0) {
            g_aedge[2 * h]     = r0[g][0] + r0[g][1] + r0[g][2] + r0[g][3];
            g_aedge[2 * h + 1] = r1[g][0] + r1[g][1] + r1[g][2] + r1[g][3];
        }
    }
}

// ---------------------------------------------------------------------------
// K3: counting-sort scatter + last-arriver computes per-node softmax stats
//     (online max/denom), and resets cursor/done for the next replay.
// ---------------------------------------------------------------------------
__global__ void k3_scatter_stats(const int* __restrict__ node_idx,
                                 const int* __restrict__ hedge_idx) {
    int e = blockIdx.x * 256 + threadIdx.x;
    if (e >= EE) return;
    int n = node_idx[e], h = hedge_idx[e];
    int pos = g_nstart[n] + atomicAdd(&g_cursor[n], 1);
    g_sh[pos] = h;
    __threadfence();
    int deg = g_Dn[n];
    if (atomicAdd(&g_done[n], 1) == deg - 1) {
        __threadfence();
        g_cursor[n] = 0; g_done[n] = 0;       // self-reset (no more writers for n)
        int start = g_nstart[n];
        float d10 = g_d1[2 * n], d11 = g_d1[2 * n + 1];
        float m0 = -1e30f, m1 = -1e30f, s0 = 0.f, s1 = 0.f;
        for (int j = 0; j < deg; j++) {
            int hh = g_sh[start + j];
            float2 ae = *(const float2*)(g_aedge + 2 * hh);
            float v0 = d10 + ae.x; v0 = (v0 >= 0.f) ? v0 : 0.2f * v0;
            float v1 = d11 + ae.y; v1 = (v1 >= 0.f) ? v1 : 0.2f * v1;
            if (v0 > m0) { s0 = s0 * __expf(m0 - v0) + 1.f; m0 = v0; }
            else         { s0 += __expf(v0 - m0); }
            if (v1 > m1) { s1 = s1 * __expf(m1 - v1) + 1.f; m1 = v1; }
            else         { s1 += __expf(v1 - m1); }
        }
        *(float4*)(g_ni + n * 8)     = make_float4(d10, d11, m0, m1);
        *(float4*)(g_ni + n * 8 + 4) = make_float4(1.f / s0, 1.f / s1, (float)deg, 0.f);
    }
}

// ---------------------------------------------------------------------------
// K4: pass1 + projection fused (block per hyperedge, 128 threads):
//     4 groups x 32 lanes; each lane loads uint2 (4 halfs) so one warp covers
//     a full 256B node row in one LDG.64; 4 incidences per inner iteration.
//     agg = (1/cnt) * sum alpha_e * x_fp16[n_e];  m = agg @ W -> g_mh (fp16)
// ---------------------------------------------------------------------------
__global__ void k4_pass1m(const int* __restrict__ node_idx,
                          const float* __restrict__ W) {
    int h = blockIdx.x, t = threadIdx.x;
    int s = g_hstart[h];
    int cnt = g_hstart[h + 1] - s;
    if (cnt == 0) { g_mh[h * 128 + t] = __float2half(0.f); return; }
    float2 ae = *(const float2*)(g_aedge + 2 * h);

    int grp  = t >> 5;            // 0..3: which incidence within a quad
    int lane = t & 31;            // owns halfs [lane*4, lane*4+4) of the row
    int bsel = lane >> 4;         // batch of those 4 halfs

    __shared__ int   sn[128];
    __shared__ float sa[2][128];
    __shared__ __align__(16) float red[4][32][4];
    __shared__ float sA[128];

    float4 acc = make_float4(0.f, 0.f, 0.f, 0.f);
    for (int base = 0; base < cnt; base += 128) {
        int mlen = min(128, cnt - base);
        __syncthreads();
        if (t < mlen) {
            int n = node_idx[s + base + t];
            float4 na = *(const float4*)(g_ni + n * 8);
            float4 nb = *(const float4*)(g_ni + n * 8 + 4);
            float v0 = na.x + ae.x; v0 = (v0 >= 0.f) ? v0 : 0.2f * v0;
            float v1 = na.y + ae.y; v1 = (v1 >= 0.f) ? v1 : 0.2f * v1;
            sn[t]    = n;
            sa[0][t] = __expf(v0 - na.z) * nb.x;
            sa[1][t] = __expf(v1 - na.w) * nb.y;
        }
        __syncthreads();
        for (int i = grp; i < mlen; i += 4) {
            int n = sn[i];
            float a = sa[bsel][i];
            uint2 raw = *(const uint2*)(g_xh + (size_t)n * 128 + lane * 4);
            float2 u = __half22float2(*(const __half2*)&raw.x);
            float2 v = __half22float2(*(const __half2*)&raw.y);
            acc.x += a * u.x; acc.y += a * u.y;
            acc.z += a * v.x; acc.w += a * v.y;
        }
    }
    *(float4*)red[grp][lane] = acc;
    __syncthreads();
    if (grp == 0) {
        float4 r0 = *(float4*)red[0][lane];
        float4 r1 = *(float4*)red[1][lane];
        float4 r2 = *(float4*)red[2][lane];
        float4 r3 = *(float4*)red[3][lane];
        float inv = 1.0f / (float)cnt;
        sA[lane * 4 + 0] = (r0.x + r1.x + r2.x + r3.x) * inv;
        sA[lane * 4 + 1] = (r0.y + r1.y + r2.y + r3.y) * inv;
        sA[lane * 4 + 2] = (r0.z + r1.z + r2.z + r3.z) * inv;
        sA[lane * 4 + 3] = (r0.w + r1.w + r2.w + r3.w) * inv;
    }
    __syncthreads();
    // projection: thread t = (b, d); m[b][d] = sum_c agg[b][c] * W[c][d]
    int d = t & 63;
    const float* arow = sA + (t >> 6) * 64;
    float m = 0.f;
#pragma unroll 8
    for (int c = 0; c < 64; c++)
        m += arow[c] * __ldg(W + c * 64 + d);
    g_mh[h * 128 + t] = __float2half(m);
}

// ---------------------------------------------------------------------------
// K5: pass2: out[b][n][c] = deg * sum alpha_e * m_fp16[h_e] (warp per node)
//     h / alpha staged through per-warp smem (LDS broadcast, no SHFL chain);
//     also resets g_Dn for the next replay.
// ---------------------------------------------------------------------------
__global__ void k5_pass2(float* __restrict__ out) {
    int wip  = threadIdx.x >> 5;                       // warp in block (0..7)
    int gw   = (blockIdx.x * blockDim.x + threadIdx.x) >> 5;
    int lane = threadIdx.x & 31;
    __shared__ int    sh_h[8][32];
    __shared__ float2 sh_a[8][32];
    if (gw >= NN) return;
    int n = gw, deg = g_Dn[n];
    int start = g_nstart[n];
    float4 na = *(const float4*)(g_ni + n * 8);
    float4 nb = *(const float4*)(g_ni + n * 8 + 4);
    int moff = (lane >> 4) * 64 + (lane & 15) * 4;
    int asel = (lane >> 4);                            // which alpha component
    float4 acc = make_float4(0.f, 0.f, 0.f, 0.f);

    for (int base = 0; base < deg; base += 32) {
        int cnt = min(32, deg - base);
        if (lane < cnt) {
            int h = g_sh[start + base + lane];
            float2 aev = *(const float2*)(g_aedge + 2 * h);
            float v0 = na.x + aev.x; v0 = (v0 >= 0.f) ? v0 : 0.2f * v0;
            float v1 = na.y + aev.y; v1 = (v1 >= 0.f) ? v1 : 0.2f * v1;
            sh_h[wip][lane] = h;
            sh_a[wip][lane] = make_float2(__expf(v0 - na.z) * nb.x,
                                          __expf(v1 - na.w) * nb.y);
        }
        __syncwarp();
        for (int i = 0; i < cnt; i++) {
            int   hh = sh_h[wip][i];
            float aa = ((const float*)&sh_a[wip][i])[asel];
            uint2 raw = *(const uint2*)(g_mh + (size_t)hh * 128 + moff);
            float2 u = __half22float2(*(const __half2*)&raw.x);
            float2 v = __half22float2(*(const __half2*)&raw.y);
            acc.x += aa * u.x; acc.y += aa * u.y;
            acc.z += aa * v.x; acc.w += aa * v.y;
        }
        __syncwarp();
    }
    if (lane == 0) g_Dn[n] = 0;       // self-reset for next replay
    float dn = (float)deg;
    int b  = lane >> 4;
    int c0 = (lane & 15) * 4;
    float4 o = make_float4(dn * acc.x, dn * acc.y, dn * acc.z, dn * acc.w);
    *(float4*)(out + (size_t)b * NN * 64 + (size_t)n * 64 + c0) = o;
}

// ---------------------------------------------------------------------------
// Launch: 5 kernels
// ---------------------------------------------------------------------------
extern "C" void kernel_launch(void* const* d_in, const int* in_sizes, int n_in,
                              void* d_out, int out_size) {
    const float* x         = (const float*)d_in[0];   // [B,N,C]
    const float* weight    = (const float*)d_in[1];   // [C,C]
    const float* att       = (const float*)d_in[2];   // [2C]
    const int*   node_idx  = (const int*)d_in[3];     // [E]
    const int*   hedge_idx = (const int*)d_in[4];     // [E] sorted
    float*       out       = (float*)d_out;           // [B,N,C]

    k1_prep<<<1 + DEG_BLOCKS + PREP_BLOCKS, 256>>>(x, weight, att, node_idx, hedge_idx);
    k2_scan_aedge<<<626, 1024>>>(node_idx);
    k3_scatter_stats<<<DEG_BLOCKS, 256>>>(node_idx, hedge_idx);
    k4_pass1m<<<HH, 128>>>(node_idx, weight);
    k5_pass2<<<(NN * 32 + 255) / 256, 256>>>(out);
}